// round 7
// baseline (speedup 1.0000x reference)
#include <cuda_runtime.h>
#include <cstdint>
#include <cstddef>

// LSTM autoencoder, fused persistent kernel, round 7.
// R7 = R6 dataflow + in-warp activation fusion: thread t computes gate row
// g = role*64 + warp*8 + jl (role = lane>>3), so all 4 gates of (b, j) live in
// one warp. After each dot phase, shfl.sync routes gates to owner lanes
// (lane<16) which hold cell states and write h directly. 2 barriers/step.
// 128 CTAs x 256 threads; each CTA owns 2 batch elements.

#define Tn 1024

// smem float offsets
#define OFF_WA   0        // dec Whh1 blocked [16c][256 tp][4]
#define OFF_WB   16384    // dec FC blocked [16c][128o][4]
#define OFF_FCB  24576    // [128]
#define OFF_XW   24704    // [2][512] XW double buffer (permuted by tp)
#define OFF_H0   25728    // [2 parity][2 batch][64]
#define OFF_H1   25984    // [2 batch][64]
#define SMEM_FLOATS 26112 // 104448 bytes

__device__ __align__(16) float g_M[256 * 64];             // dec_Wih0 @ fcW
__device__ __align__(16) float g_XW[128u * 1024u * 512u]; // enc L0 x-part, bias folded, tp-permuted

__device__ __forceinline__ void fma2(unsigned long long& acc,
                                     unsigned long long a, unsigned long long b) {
    asm("fma.rn.f32x2 %0, %1, %2, %3;" : "=l"(acc) : "l"(a), "l"(b), "l"(acc));
}
__device__ __forceinline__ float psum(unsigned long long v) {
    float lo, hi;
    asm("mov.b64 {%0, %1}, %2;" : "=f"(lo), "=f"(hi) : "l"(v));
    return lo + hi;
}
__device__ __forceinline__ float sigm_f(float v) {
    return __fdividef(1.f, 1.f + __expf(-v));
}
__device__ __forceinline__ float tanh_f(float v) {
    float a = fabsf(v);
    float e = __expf(-2.f * a);
    float r = __fdividef(1.f - e, 1.f + e);
    return v < 0.f ? -r : r;
}
__device__ __forceinline__ float cellact(float gi, float gf, float gg, float go, float& c) {
    c = sigm_f(gf) * c + sigm_f(gi) * tanh_f(gg);
    return sigm_f(go) * tanh_f(c);
}

// permuted thread position owning gate row gg
__device__ __host__ __forceinline__ int tpos(int gg) {
    int role = gg >> 6, j = gg & 63;
    return (j >> 3) * 32 + role * 8 + (j & 7);
}

// gather the 4 role values for this lane's jl: src lane r*8+jl
#define GATHER4(dst, src) { \
    dst[0] = __shfl_sync(0xffffffffu, src, jl); \
    dst[1] = __shfl_sync(0xffffffffu, src, 8 + jl); \
    dst[2] = __shfl_sync(0xffffffffu, src, 16 + jl); \
    dst[3] = __shfl_sync(0xffffffffu, src, 24 + jl); }

__global__ void prep_kernel(const float* __restrict__ dW0i, const float* __restrict__ fcW) {
    int id = blockIdx.x * blockDim.x + threadIdx.x;  // 0..16383
    int g = id >> 6, j = id & 63;
    float acc = 0.f;
    #pragma unroll 4
    for (int d = 0; d < 128; d++)
        acc = fmaf(dW0i[g * 128 + d], fcW[d * 64 + j], acc);
    g_M[id] = acc;
}

// XW[pair][s][e][tp(gate)] = x[b,s,:] . Wih0[gate,:] + eb0i + eb0h
__global__ void __launch_bounds__(256, 1)
prep_x_kernel(const float* __restrict__ x, const float* __restrict__ eW0i,
              const float* __restrict__ eb0i, const float* __restrict__ eb0h) {
    __shared__ float sx[32 * 128];
    const int b  = blockIdx.x;     // 0..255
    const int ch = blockIdx.y;     // 0..31 (32-step chunk)
    const int t  = threadIdx.x;    // gate 0..255
    const int tp = tpos(t);

    for (int i = t; i < 32 * 128; i += 256)
        sx[i] = x[((size_t)b * Tn + ch * 32) * 128 + i];

    unsigned long long w[64];
    const ulonglong2* p = (const ulonglong2*)(eW0i + t * 128);
    #pragma unroll
    for (int i = 0; i < 32; i++) { ulonglong2 v = p[i]; w[2*i] = v.x; w[2*i+1] = v.y; }
    const float bias = eb0i[t] + eb0h[t];
    __syncthreads();

    for (int s = 0; s < 32; s++) {
        const ulonglong2* xp = (const ulonglong2*)(sx + s * 128);
        unsigned long long q0 = 0ull, q1 = 0ull;
        #pragma unroll
        for (int i = 0; i < 32; i++) {
            ulonglong2 v = xp[i];
            fma2(q0, w[2*i], v.x);
            fma2(q1, w[2*i+1], v.y);
        }
        g_XW[(((size_t)(b >> 1) * Tn + ch * 32 + s) * 2 + (b & 1)) * 256 + tp] =
            psum(q0) + psum(q1) + bias;
    }
}

__global__ void __launch_bounds__(256, 1)
lstm_ae_kernel(const float* __restrict__ x,
               const float* __restrict__ eW0i, const float* __restrict__ eW0h,
               const float* __restrict__ eb0i, const float* __restrict__ eb0h,
               const float* __restrict__ eW1i, const float* __restrict__ eW1h,
               const float* __restrict__ eb1i, const float* __restrict__ eb1h,
               const float* __restrict__ dW0i, const float* __restrict__ dW0h,
               const float* __restrict__ db0i, const float* __restrict__ db0h,
               const float* __restrict__ dW1i, const float* __restrict__ dW1h,
               const float* __restrict__ db1i, const float* __restrict__ db1h,
               const float* __restrict__ fcW,  const float* __restrict__ fcb,
               float* __restrict__ out)
{
    extern __shared__ float sm[];
    float* sWA  = sm + OFF_WA;
    float* sWB  = sm + OFF_WB;
    float* sFCb = sm + OFF_FCB;
    float* sXW  = sm + OFF_XW;
    float* sH0  = sm + OFF_H0;
    float* sH1  = sm + OFF_H1;

    const int t    = threadIdx.x;
    const int b0   = blockIdx.x * 2;
    const int lane = t & 31, warp = t >> 5;
    const int jl   = lane & 7;
    const int role = lane >> 3;          // gate type i,f,g,o
    const int j    = warp * 8 + jl;      // hidden index 0..63
    const int g    = role * 64 + j;      // gate row (permutation of 0..255)
    const bool own = lane < 16;          // act owner lanes
    const int bb   = (lane >> 3) & 1;    // owner batch

    float c0 = 0.f, c1 = 0.f;            // cell states held by owner lanes (bb, j)

    // ---- stage decoder smem weights (permuted-blocked) ----
    for (int idx = t; idx < 256 * 64; idx += 256) {
        int gg = idx >> 6, k = idx & 63;
        sWA[(k >> 2) * 1024 + tpos(gg) * 4 + (k & 3)] = dW1h[idx];
    }
    for (int idx = t; idx < 128 * 64; idx += 256) {
        int o = idx >> 6, k = idx & 63;
        sWB[(k >> 2) * 512 + o * 4 + (k & 3)] = fcW[idx];
    }
    if (t < 128) sFCb[t] = fcb[t];
    // zero h state
    if (t < 128) { sH0[t] = 0.f; sH0[128 + t] = 0.f; }
    else if (t < 256) sH1[t - 128] = 0.f;

    // ================= ENCODER =================
    {
        unsigned long long wH0[32], wI1[32], wH1[32];   // rows g of Whh0, Wih1, Whh1
        {
            const ulonglong2* p = (const ulonglong2*)(eW0h + g * 64);
            #pragma unroll
            for (int i = 0; i < 16; i++) { ulonglong2 v = p[i]; wH0[2*i] = v.x; wH0[2*i+1] = v.y; }
            const ulonglong2* q = (const ulonglong2*)(eW1i + g * 64);
            #pragma unroll
            for (int i = 0; i < 16; i++) { ulonglong2 v = q[i]; wI1[2*i] = v.x; wI1[2*i+1] = v.y; }
            const ulonglong2* r = (const ulonglong2*)(eW1h + g * 64);
            #pragma unroll
            for (int i = 0; i < 16; i++) { ulonglong2 v = r[i]; wH1[2*i] = v.x; wH1[2*i+1] = v.y; }
        }
        const float bias1 = eb1i[g] + eb1h[g];
        const size_t xwbase = (size_t)blockIdx.x * Tn * 512;

        // prologue: prefetch XW steps 0,1
        #pragma unroll
        for (int s = 0; s < 2; s++) {
            if (t < 128) {
                const float* src = g_XW + xwbase + (size_t)s * 512 + t * 4;
                uint32_t dst = (uint32_t)__cvta_generic_to_shared(sXW + s * 512 + t * 4);
                asm volatile("cp.async.cg.shared.global [%0], [%1], 16;" :: "r"(dst), "l"(src) : "memory");
            }
            asm volatile("cp.async.commit_group;" ::: "memory");
        }
        asm volatile("cp.async.wait_group 1;" ::: "memory");
        __syncthreads();

        for (int s = 0; s < Tn; s++) {
            const int par = s & 1;
            const float* xw  = sXW + par * 512;
            const float* h0r = sH0 + par * 128;
            float*       h0w = sH0 + (par ^ 1) * 128;

            // ---- P1: gates0 = XW + Whh0@h0 ; p = Whh1@h1 + bias1 ; act0 ----
            float p0, p1;
            {
                const ulonglong2* h0a = (const ulonglong2*)(h0r);
                const ulonglong2* h0b = (const ulonglong2*)(h0r + 64);
                unsigned long long qa0 = 0, qa1 = 0, qb0 = 0, qb1 = 0;
                #pragma unroll
                for (int i = 0; i < 16; i++) {
                    ulonglong2 va = h0a[i], vb = h0b[i];
                    fma2(qa0, wH0[2*i], va.x); fma2(qa1, wH0[2*i+1], va.y);
                    fma2(qb0, wH0[2*i], vb.x); fma2(qb1, wH0[2*i+1], vb.y);
                }
                float ga0 = xw[t]       + psum(qa0) + psum(qa1);
                float gb0 = xw[256 + t] + psum(qb0) + psum(qb1);

                const ulonglong2* h1a = (const ulonglong2*)(sH1);
                const ulonglong2* h1b = (const ulonglong2*)(sH1 + 64);
                unsigned long long r0 = 0, r1 = 0, r2 = 0, r3 = 0;
                #pragma unroll
                for (int i = 0; i < 16; i++) {
                    ulonglong2 va = h1a[i], vb = h1b[i];
                    fma2(r0, wH1[2*i], va.x); fma2(r1, wH1[2*i+1], va.y);
                    fma2(r2, wH1[2*i], vb.x); fma2(r3, wH1[2*i+1], vb.y);
                }
                p0 = psum(r0) + psum(r1) + bias1;
                p1 = psum(r2) + psum(r3) + bias1;

                float A[4], Bv[4];
                GATHER4(A, ga0); GATHER4(Bv, gb0);
                if (own) {
                    float gi = bb ? Bv[0] : A[0], gf = bb ? Bv[1] : A[1];
                    float gg = bb ? Bv[2] : A[2], go = bb ? Bv[3] : A[3];
                    h0w[bb * 64 + j] = cellact(gi, gf, gg, go, c0);
                }
            }
            __syncthreads();

            // ---- P2: prefetch XW[s+2]; gates1 = Wih1@h0[s] + p ; act1 ----
            {
                if (t < 128 && s + 2 < Tn) {
                    const float* src = g_XW + xwbase + (size_t)(s + 2) * 512 + t * 4;
                    uint32_t dst = (uint32_t)__cvta_generic_to_shared(sXW + par * 512 + t * 4);
                    asm volatile("cp.async.cg.shared.global [%0], [%1], 16;" :: "r"(dst), "l"(src) : "memory");
                }
                asm volatile("cp.async.commit_group;" ::: "memory");

                const ulonglong2* h0a = (const ulonglong2*)(h0w);
                const ulonglong2* h0b = (const ulonglong2*)(h0w + 64);
                unsigned long long qa0 = 0, qa1 = 0, qb0 = 0, qb1 = 0;
                #pragma unroll
                for (int i = 0; i < 16; i++) {
                    ulonglong2 va = h0a[i], vb = h0b[i];
                    fma2(qa0, wI1[2*i], va.x); fma2(qa1, wI1[2*i+1], va.y);
                    fma2(qb0, wI1[2*i], vb.x); fma2(qb1, wI1[2*i+1], vb.y);
                }
                float ga1 = psum(qa0) + psum(qa1) + p0;
                float gb1 = psum(qb0) + psum(qb1) + p1;

                float C[4], D[4];
                GATHER4(C, ga1); GATHER4(D, gb1);
                if (own) {
                    float gi = bb ? D[0] : C[0], gf = bb ? D[1] : C[1];
                    float gg = bb ? D[2] : C[2], go = bb ? D[3] : C[3];
                    sH1[bb * 64 + j] = cellact(gi, gf, gg, go, c1);
                }
            }
            asm volatile("cp.async.wait_group 1;" ::: "memory");
            __syncthreads();
        }
        asm volatile("cp.async.wait_group 0;" ::: "memory");
    }

    // ================= TRANSITION =================
    // h0[T-1] is in sH0 parity buffer 0 (s=1023: wrote par^1=0); h1[T-1] in sH1.
    if (own) { c0 = tanh_f(c0); c1 = tanh_f(c1); }
    if (t < 128)      sH0[t]       = tanh_f(sH0[t]);        // buffer 0 (decoder s=0 reads par 0)
    else              sH1[t - 128] = tanh_f(sH1[t - 128]);
    unsigned long long wA[64];  // [0..31] M row (over h1), [32..63] Whh0 row (over h0)
    unsigned long long wC[32];  // Wih1 row (over h0)
    {
        const ulonglong2* p = (const ulonglong2*)(g_M + g * 64);
        #pragma unroll
        for (int i = 0; i < 16; i++) { ulonglong2 v = p[i]; wA[2*i] = v.x; wA[2*i+1] = v.y; }
        const ulonglong2* q = (const ulonglong2*)(dW0h + g * 64);
        #pragma unroll
        for (int i = 0; i < 16; i++) { ulonglong2 v = q[i]; wA[32+2*i] = v.x; wA[33+2*i] = v.y; }
        const ulonglong2* r = (const ulonglong2*)(dW1i + g * 64);
        #pragma unroll
        for (int i = 0; i < 16; i++) { ulonglong2 v = r[i]; wC[2*i] = v.x; wC[2*i+1] = v.y; }
    }
    const float bias0 = db0i[g] + db0h[g];
    float b0fold;
    {
        float a = 0.f;
        #pragma unroll 4
        for (int d = 0; d < 128; d++) a = fmaf(dW0i[g * 128 + d], fcb[d], a);
        b0fold = bias0 + a;   // bias0 + Wih0 @ fcb
    }
    const float bias1 = db1i[g] + db1h[g];
    __syncthreads();

    // ================= DECODER =================
    const int oF = t & 127, bF = t >> 7;
    const ulonglong2* whp = (const ulonglong2*)sWA;   // Whh1 blocked [c*256 + t]
    const ulonglong2* wfc = (const ulonglong2*)sWB;   // FC blocked  [c*128 + oF]
    const float fcbO = sFCb[oF];

    for (int s = 0; s < Tn; s++) {
        const int par = s & 1;
        const float* h0r = sH0 + par * 128;
        float*       h0w = sH0 + (par ^ 1) * 128;

        // ---- P1: gates0 (regs) + p (smem Whh1) + deferred FC ; act0 ----
        float p0, p1;
        {
            const ulonglong2* h0a = (const ulonglong2*)(h0r);
            const ulonglong2* h0b = (const ulonglong2*)(h0r + 64);
            const ulonglong2* h1a = (const ulonglong2*)(sH1);
            const ulonglong2* h1b = (const ulonglong2*)(sH1 + 64);
            unsigned long long a0 = 0, a1 = 0, c0q = 0, c1q = 0;
            #pragma unroll
            for (int i = 0; i < 16; i++) {
                ulonglong2 va = h0a[i], vb = h0b[i];
                fma2(a0, wA[32 + 2*i], va.x); fma2(a1, wA[33 + 2*i], va.y);
                fma2(c0q, wA[32 + 2*i], vb.x); fma2(c1q, wA[33 + 2*i], vb.y);
            }
            float ga0, gb0;
            if (s > 0) {
                #pragma unroll
                for (int i = 0; i < 16; i++) {
                    ulonglong2 va = h1a[i], vb = h1b[i];
                    fma2(a0, wA[2*i], va.x); fma2(a1, wA[2*i+1], va.y);
                    fma2(c0q, wA[2*i], vb.x); fma2(c1q, wA[2*i+1], vb.y);
                }
                ga0 = psum(a0) + psum(a1) + b0fold;
                gb0 = psum(c0q) + psum(c1q) + b0fold;
            } else {
                ga0 = psum(a0) + psum(a1) + bias0;
                gb0 = psum(c0q) + psum(c1q) + bias0;
            }

            // p = Whh1 @ h1[s-1] + bias1 (blocked smem, conflict-free)
            {
                unsigned long long q00 = 0, q01 = 0, q10 = 0, q11 = 0;
                #pragma unroll
                for (int i = 0; i < 8; i++) {
                    ulonglong2 w0c = whp[(2*i) * 256 + t];
                    ulonglong2 w1c = whp[(2*i+1) * 256 + t];
                    ulonglong2 va0 = h1a[2*i], va1 = h1a[2*i+1];
                    ulonglong2 vb0 = h1b[2*i], vb1 = h1b[2*i+1];
                    fma2(q00, w0c.x, va0.x); fma2(q01, w0c.y, va0.y);
                    fma2(q10, w0c.x, vb0.x); fma2(q11, w0c.y, vb0.y);
                    fma2(q00, w1c.x, va1.x); fma2(q01, w1c.y, va1.y);
                    fma2(q10, w1c.x, vb1.x); fma2(q11, w1c.y, vb1.y);
                }
                p0 = psum(q00) + psum(q01) + bias1;
                p1 = psum(q10) + psum(q11) + bias1;
            }

            // deferred FC of h1[s-1] -> out[s-1]
            if (s > 0) {
                const ulonglong2* hp = (const ulonglong2*)(sH1 + bF * 64);
                unsigned long long f0 = 0, f1 = 0;
                #pragma unroll
                for (int i = 0; i < 8; i++) {
                    ulonglong2 wc0 = wfc[(2*i) * 128 + oF];
                    ulonglong2 wc1 = wfc[(2*i+1) * 128 + oF];
                    ulonglong2 h0v = hp[2*i], h1v = hp[2*i+1];
                    fma2(f0, wc0.x, h0v.x); fma2(f1, wc0.y, h0v.y);
                    fma2(f0, wc1.x, h1v.x); fma2(f1, wc1.y, h1v.y);
                }
                out[((size_t)(b0 + bF) * Tn + (s - 1)) * 128 + oF] = psum(f0) + psum(f1) + fcbO;
            }

            float A[4], Bv[4];
            GATHER4(A, ga0); GATHER4(Bv, gb0);
            if (own) {
                float gi = bb ? Bv[0] : A[0], gf = bb ? Bv[1] : A[1];
                float gg = bb ? Bv[2] : A[2], go = bb ? Bv[3] : A[3];
                h0w[bb * 64 + j] = cellact(gi, gf, gg, go, c0);
            }
        }
        __syncthreads();

        // ---- P2: gates1 = Wih1@h0[s] (regs) + p ; act1 ----
        {
            const ulonglong2* h0a = (const ulonglong2*)(h0w);
            const ulonglong2* h0b = (const ulonglong2*)(h0w + 64);
            unsigned long long qa0 = 0, qa1 = 0, qb0 = 0, qb1 = 0;
            #pragma unroll
            for (int i = 0; i < 16; i++) {
                ulonglong2 va = h0a[i], vb = h0b[i];
                fma2(qa0, wC[2*i], va.x); fma2(qa1, wC[2*i+1], va.y);
                fma2(qb0, wC[2*i], vb.x); fma2(qb1, wC[2*i+1], vb.y);
            }
            float ga1 = psum(qa0) + psum(qa1) + p0;
            float gb1 = psum(qb0) + psum(qb1) + p1;

            float C[4], D[4];
            GATHER4(C, ga1); GATHER4(D, gb1);
            if (own) {
                float gi = bb ? D[0] : C[0], gf = bb ? D[1] : C[1];
                float gg = bb ? D[2] : C[2], go = bb ? D[3] : C[3];
                sH1[bb * 64 + j] = cellact(gi, gf, gg, go, c1);
            }
        }
        __syncthreads();
    }

    // final FC for h1[T-1]
    {
        const ulonglong2* hp = (const ulonglong2*)(sH1 + bF * 64);
        unsigned long long f0 = 0, f1 = 0;
        #pragma unroll
        for (int i = 0; i < 8; i++) {
            ulonglong2 wc0 = wfc[(2*i) * 128 + oF];
            ulonglong2 wc1 = wfc[(2*i+1) * 128 + oF];
            ulonglong2 h0v = hp[2*i], h1v = hp[2*i+1];
            fma2(f0, wc0.x, h0v.x); fma2(f1, wc0.y, h0v.y);
            fma2(f0, wc1.x, h1v.x); fma2(f1, wc1.y, h1v.y);
        }
        out[((size_t)(b0 + bF) * Tn + (Tn - 1)) * 128 + oF] = psum(f0) + psum(f1) + fcbO;
    }
}

extern "C" void kernel_launch(void* const* d_in, const int* in_sizes, int n_in,
                              void* d_out, int out_size) {
    (void)in_sizes; (void)n_in; (void)out_size;
    const float* x    = (const float*)d_in[0];
    const float* eW0i = (const float*)d_in[1];
    const float* eW0h = (const float*)d_in[2];
    const float* eb0i = (const float*)d_in[3];
    const float* eb0h = (const float*)d_in[4];
    const float* eW1i = (const float*)d_in[5];
    const float* eW1h = (const float*)d_in[6];
    const float* eb1i = (const float*)d_in[7];
    const float* eb1h = (const float*)d_in[8];
    const float* dW0i = (const float*)d_in[9];
    const float* dW0h = (const float*)d_in[10];
    const float* db0i = (const float*)d_in[11];
    const float* db0h = (const float*)d_in[12];
    const float* dW1i = (const float*)d_in[13];
    const float* dW1h = (const float*)d_in[14];
    const float* db1i = (const float*)d_in[15];
    const float* db1h = (const float*)d_in[16];
    const float* fcW  = (const float*)d_in[17];
    const float* fcb  = (const float*)d_in[18];

    prep_kernel<<<64, 256>>>(dW0i, fcW);
    dim3 pgrid(256, 32);
    prep_x_kernel<<<pgrid, 256>>>(x, eW0i, eb0i, eb0h);

    cudaFuncSetAttribute(lstm_ae_kernel, cudaFuncAttributeMaxDynamicSharedMemorySize,
                         SMEM_FLOATS * (int)sizeof(float));
    lstm_ae_kernel<<<128, 256, SMEM_FLOATS * sizeof(float)>>>(
        x, eW0i, eW0h, eb0i, eb0h, eW1i, eW1h, eb1i, eb1h,
        dW0i, dW0h, db0i, db0h, dW1i, dW1h, db1i, db1h,
        fcW, fcb, (float*)d_out);
}

// round 8
// speedup vs baseline: 1.4167x; 1.4167x over previous
#include <cuda_runtime.h>
#include <cstdint>
#include <cstddef>

// LSTM autoencoder, fused persistent kernel, round 8.
// R8 = R6 + merged encoder phases: gates1[s] and gates0[s+1] (which needs only
// h0[s]) computed in one dot phase sharing the h0 loads; act1[s] and act0[s+1]
// are independent -> one act phase with disjoint thread halves (t<128 own c1,
// t>=128 own c0). Encoder: 2 barriers/step. Decoder: R6-verbatim (4 barriers,
// serial chain). 128 CTAs x 256 threads; each CTA owns 2 batch elements.

#define Tn 1024

// smem float offsets
#define OFF_WA   0        // dec Whh1 blocked [16c][256g][4]
#define OFF_WB   16384    // dec FC blocked [16c][128o][4]
#define OFF_FCB  24576    // [128]
#define OFF_XW   24704    // [2][512] XW double buffer
#define OFF_H0   25728    // [2 parity][2 batch][64] (encoder uses buffer 0)
#define OFF_H1   25984    // [2 batch][64]
#define OFF_G    26112    // [1024] gate scratch: enc gates1 @0, gates0 @512
#define SMEM_FLOATS 27136 // 108544 bytes

__device__ __align__(16) float g_M[256 * 64];             // dec_Wih0 @ fcW
__device__ __align__(16) float g_XW[128u * 1024u * 512u]; // enc L0 x-part, bias folded

__device__ __forceinline__ void fma2(unsigned long long& acc,
                                     unsigned long long a, unsigned long long b) {
    asm("fma.rn.f32x2 %0, %1, %2, %3;" : "=l"(acc) : "l"(a), "l"(b), "l"(acc));
}
__device__ __forceinline__ float psum(unsigned long long v) {
    float lo, hi;
    asm("mov.b64 {%0, %1}, %2;" : "=f"(lo), "=f"(hi) : "l"(v));
    return lo + hi;
}
__device__ __forceinline__ float sigm_f(float v) {
    return __fdividef(1.f, 1.f + __expf(-v));
}
__device__ __forceinline__ float tanh_f(float v) {
    float a = fabsf(v);
    float e = __expf(-2.f * a);
    float r = __fdividef(1.f - e, 1.f + e);
    return v < 0.f ? -r : r;
}
__device__ __forceinline__ float cellact(float gi, float gf, float gg, float go, float& c) {
    c = sigm_f(gf) * c + sigm_f(gi) * tanh_f(gg);
    return sigm_f(go) * tanh_f(c);
}

__global__ void prep_kernel(const float* __restrict__ dW0i, const float* __restrict__ fcW) {
    int id = blockIdx.x * blockDim.x + threadIdx.x;  // 0..16383
    int g = id >> 6, j = id & 63;
    float acc = 0.f;
    #pragma unroll 4
    for (int d = 0; d < 128; d++)
        acc = fmaf(dW0i[g * 128 + d], fcW[d * 64 + j], acc);
    g_M[id] = acc;
}

// XW[pair][s][e][g] = x[b,s,:] . Wih0[g,:] + eb0i[g] + eb0h[g]
__global__ void __launch_bounds__(256, 1)
prep_x_kernel(const float* __restrict__ x, const float* __restrict__ eW0i,
              const float* __restrict__ eb0i, const float* __restrict__ eb0h) {
    __shared__ float sx[32 * 128];
    const int b  = blockIdx.x;     // 0..255
    const int ch = blockIdx.y;     // 0..31
    const int t  = threadIdx.x;    // gate 0..255

    for (int i = t; i < 32 * 128; i += 256)
        sx[i] = x[((size_t)b * Tn + ch * 32) * 128 + i];

    unsigned long long w[64];
    const ulonglong2* p = (const ulonglong2*)(eW0i + t * 128);
    #pragma unroll
    for (int i = 0; i < 32; i++) { ulonglong2 v = p[i]; w[2*i] = v.x; w[2*i+1] = v.y; }
    const float bias = eb0i[t] + eb0h[t];
    __syncthreads();

    for (int s = 0; s < 32; s++) {
        const ulonglong2* xp = (const ulonglong2*)(sx + s * 128);
        unsigned long long q0 = 0ull, q1 = 0ull;
        #pragma unroll
        for (int i = 0; i < 32; i++) {
            ulonglong2 v = xp[i];
            fma2(q0, w[2*i], v.x);
            fma2(q1, w[2*i+1], v.y);
        }
        g_XW[(((size_t)(b >> 1) * Tn + ch * 32 + s) * 2 + (b & 1)) * 256 + t] =
            psum(q0) + psum(q1) + bias;
    }
}

__global__ void __launch_bounds__(256, 1)
lstm_ae_kernel(const float* __restrict__ x,
               const float* __restrict__ eW0i, const float* __restrict__ eW0h,
               const float* __restrict__ eb0i, const float* __restrict__ eb0h,
               const float* __restrict__ eW1i, const float* __restrict__ eW1h,
               const float* __restrict__ eb1i, const float* __restrict__ eb1h,
               const float* __restrict__ dW0i, const float* __restrict__ dW0h,
               const float* __restrict__ db0i, const float* __restrict__ db0h,
               const float* __restrict__ dW1i, const float* __restrict__ dW1h,
               const float* __restrict__ db1i, const float* __restrict__ db1h,
               const float* __restrict__ fcW,  const float* __restrict__ fcb,
               float* __restrict__ out)
{
    extern __shared__ float sm[];
    float* sWA  = sm + OFF_WA;
    float* sWB  = sm + OFF_WB;
    float* sFCb = sm + OFF_FCB;
    float* sXW  = sm + OFF_XW;
    float* sH0  = sm + OFF_H0;
    float* sH1  = sm + OFF_H1;
    float* sG   = sm + OFF_G;

    const int t  = threadIdx.x;
    const int b0 = blockIdx.x * 2;
    const int aj = t & 63;
    const int ab = (t >> 6) & 1;

    float c0 = 0.f, c1 = 0.f;

    // ---- stage decoder smem weights up front ----
    for (int idx = t; idx < 256 * 64; idx += 256) {
        int g = idx >> 6, k = idx & 63;
        sWA[(k >> 2) * 1024 + g * 4 + (k & 3)] = dW1h[idx];
    }
    for (int idx = t; idx < 128 * 64; idx += 256) {
        int o = idx >> 6, k = idx & 63;
        sWB[(k >> 2) * 512 + o * 4 + (k & 3)] = fcW[idx];
    }
    if (t < 128) { sFCb[t] = fcb[t]; sH1[t] = 0.f; }

    // ================= ENCODER =================
    {
        unsigned long long wH0[32], wI1[32], wH1[32];   // rows t of Whh0, Wih1, Whh1
        {
            const ulonglong2* p = (const ulonglong2*)(eW0h + t * 64);
            #pragma unroll
            for (int i = 0; i < 16; i++) { ulonglong2 v = p[i]; wH0[2*i] = v.x; wH0[2*i+1] = v.y; }
            const ulonglong2* q = (const ulonglong2*)(eW1i + t * 64);
            #pragma unroll
            for (int i = 0; i < 16; i++) { ulonglong2 v = q[i]; wI1[2*i] = v.x; wI1[2*i+1] = v.y; }
            const ulonglong2* r = (const ulonglong2*)(eW1h + t * 64);
            #pragma unroll
            for (int i = 0; i < 16; i++) { ulonglong2 v = r[i]; wH1[2*i] = v.x; wH1[2*i+1] = v.y; }
        }
        const float bias1 = eb1i[t] + eb1h[t];
        const size_t xwbase = (size_t)blockIdx.x * Tn * 512;

        // ---- prologue: XW[0] -> slot0; gates0[0]; act0[0]; prefetch XW[1],XW[2] ----
        if (t < 128) {
            const float* src = g_XW + xwbase + t * 4;
            uint32_t dst = (uint32_t)__cvta_generic_to_shared(sXW + t * 4);
            asm volatile("cp.async.cg.shared.global [%0], [%1], 16;" :: "r"(dst), "l"(src) : "memory");
        }
        asm volatile("cp.async.commit_group;" ::: "memory");
        asm volatile("cp.async.wait_group 0;" ::: "memory");
        __syncthreads();

        sG[512 + t] = sXW[t];          // gates0[0] = XW[0] (h0[-1]=0)
        sG[768 + t] = sXW[256 + t];
        __syncthreads();

        if (t >= 128) {                // act0[0] -> h0[0]
            int t2 = t - 128, aB = (t2 >> 6) & 1, aj2 = t2 & 63;
            const float* gq = sG + 512 + aB * 256;
            sH0[aB * 64 + aj2] = cellact(gq[aj2], gq[64 + aj2], gq[128 + aj2], gq[192 + aj2], c0);
        } else {                       // prefetch XW[1] -> slot1
            const float* src = g_XW + xwbase + (size_t)1 * 512 + t * 4;
            uint32_t dst = (uint32_t)__cvta_generic_to_shared(sXW + 512 + t * 4);
            asm volatile("cp.async.cg.shared.global [%0], [%1], 16;" :: "r"(dst), "l"(src) : "memory");
        }
        asm volatile("cp.async.commit_group;" ::: "memory");
        if (t < 128) {                 // prefetch XW[2] -> slot0
            const float* src = g_XW + xwbase + (size_t)2 * 512 + t * 4;
            uint32_t dst = (uint32_t)__cvta_generic_to_shared(sXW + t * 4);
            asm volatile("cp.async.cg.shared.global [%0], [%1], 16;" :: "r"(dst), "l"(src) : "memory");
        }
        asm volatile("cp.async.commit_group;" ::: "memory");
        __syncthreads();

        // ---- main loop: 2 phases / step ----
        for (int s = 0; s < Tn; s++) {
            // Phase A: gates1[s] = Wih1@h0[s] + Whh1@h1[s-1] + bias1
            //          gates0[s+1] = XW[s+1] + Whh0@h0[s]
            asm volatile("cp.async.wait_group 1;" ::: "memory");  // XW[s+1] landed
            {
                const float* xw = sXW + ((s + 1) & 1) * 512;
                const ulonglong2* h0a = (const ulonglong2*)(sH0);
                const ulonglong2* h0b = (const ulonglong2*)(sH0 + 64);
                const ulonglong2* h1a = (const ulonglong2*)(sH1);
                const ulonglong2* h1b = (const ulonglong2*)(sH1 + 64);
                unsigned long long qa0 = 0, qa1 = 0, qb0 = 0, qb1 = 0;   // Wih1@h0
                unsigned long long ra0 = 0, ra1 = 0, rb0 = 0, rb1 = 0;   // Whh1@h1
                unsigned long long sa0 = 0, sa1 = 0, sb0 = 0, sb1 = 0;   // Whh0@h0
                #pragma unroll
                for (int i = 0; i < 16; i++) {
                    ulonglong2 va = h0a[i], vb = h0b[i];
                    fma2(qa0, wI1[2*i], va.x); fma2(qa1, wI1[2*i+1], va.y);
                    fma2(qb0, wI1[2*i], vb.x); fma2(qb1, wI1[2*i+1], vb.y);
                    fma2(sa0, wH0[2*i], va.x); fma2(sa1, wH0[2*i+1], va.y);
                    fma2(sb0, wH0[2*i], vb.x); fma2(sb1, wH0[2*i+1], vb.y);
                    ulonglong2 wa = h1a[i], wb = h1b[i];
                    fma2(ra0, wH1[2*i], wa.x); fma2(ra1, wH1[2*i+1], wa.y);
                    fma2(rb0, wH1[2*i], wb.x); fma2(rb1, wH1[2*i+1], wb.y);
                }
                sG[t]       = psum(qa0) + psum(qa1) + psum(ra0) + psum(ra1) + bias1;
                sG[256 + t] = psum(qb0) + psum(qb1) + psum(rb0) + psum(rb1) + bias1;
                sG[512 + t] = xw[t]       + psum(sa0) + psum(sa1);
                sG[768 + t] = xw[256 + t] + psum(sb0) + psum(sb1);
            }
            __syncthreads();

            // Phase B: act1[s] (t<128) || act0[s+1] + XW prefetch (t>=128)
            if (t < 128) {
                const float* gq = sG + ab * 256;
                sH1[ab * 64 + aj] = cellact(gq[aj], gq[64 + aj], gq[128 + aj], gq[192 + aj], c1);
            } else {
                if (s + 1 < Tn) {
                    int t2 = t - 128, aB = (t2 >> 6) & 1, aj2 = t2 & 63;
                    const float* gq = sG + 512 + aB * 256;
                    sH0[aB * 64 + aj2] = cellact(gq[aj2], gq[64 + aj2], gq[128 + aj2], gq[192 + aj2], c0);
                }
                if (s + 3 < Tn) {
                    int l = t - 128;
                    const float* src = g_XW + xwbase + (size_t)(s + 3) * 512 + l * 4;
                    uint32_t dst = (uint32_t)__cvta_generic_to_shared(sXW + ((s + 1) & 1) * 512 + l * 4);
                    asm volatile("cp.async.cg.shared.global [%0], [%1], 16;" :: "r"(dst), "l"(src) : "memory");
                }
            }
            asm volatile("cp.async.commit_group;" ::: "memory");
            __syncthreads();
        }
        asm volatile("cp.async.wait_group 0;" ::: "memory");
    }

    // ================= TRANSITION =================
    // c0 lives in threads >=128 (same (ab,aj) map as decoder thread t-128); hand off via sG.
    if (t >= 128) sG[t - 128] = c0;
    __syncthreads();
    if (t < 128) {
        c0 = tanh_f(sG[t]);
        c1 = tanh_f(c1);
        sH0[t] = tanh_f(sH0[t]);   // h0[T-1], decoder parity buffer 0
        sH1[t] = tanh_f(sH1[t]);
    }
    unsigned long long wA[64];  // [0..31] M row (over h1), [32..63] Whh0 row (over h0)
    unsigned long long wC[32];  // Wih1 row (over h0)
    {
        const ulonglong2* p = (const ulonglong2*)(g_M + t * 64);
        #pragma unroll
        for (int i = 0; i < 16; i++) { ulonglong2 v = p[i]; wA[2*i] = v.x; wA[2*i+1] = v.y; }
        const ulonglong2* q = (const ulonglong2*)(dW0h + t * 64);
        #pragma unroll
        for (int i = 0; i < 16; i++) { ulonglong2 v = q[i]; wA[32+2*i] = v.x; wA[33+2*i] = v.y; }
        const ulonglong2* r = (const ulonglong2*)(dW1i + t * 64);
        #pragma unroll
        for (int i = 0; i < 16; i++) { ulonglong2 v = r[i]; wC[2*i] = v.x; wC[2*i+1] = v.y; }
    }
    const float bias0 = db0i[t] + db0h[t];
    float b0fold;
    {
        float a = 0.f;
        #pragma unroll 4
        for (int d = 0; d < 128; d++) a = fmaf(dW0i[t * 128 + d], fcb[d], a);
        b0fold = bias0 + a;   // bias0 + Wih0 @ fcb
    }
    const float bias1 = db1i[t] + db1h[t];
    __syncthreads();

    // ================= DECODER (R6-verbatim) =================
    const int oF = t & 127, bF = t >> 7;
    const ulonglong2* whp = (const ulonglong2*)sWA;   // Whh1 blocked [c*256 + t]
    const ulonglong2* wfc = (const ulonglong2*)sWB;   // FC blocked  [c*128 + oF]
    const float fcbO = sFCb[oF];

    for (int s = 0; s < Tn; s++) {
        const int par = s & 1;
        const float* h0r = sH0 + par * 128;
        float*       h0w = sH0 + (par ^ 1) * 128;

        // P1: gates0 = Whh0*h0_prev (+ M*h1_prev if s>0) + deferred FC -> out[s-1]
        {
            const ulonglong2* h0a = (const ulonglong2*)(h0r);
            const ulonglong2* h0b = (const ulonglong2*)(h0r + 64);
            const ulonglong2* h1a = (const ulonglong2*)(sH1);
            const ulonglong2* h1b = (const ulonglong2*)(sH1 + 64);
            unsigned long long a0 = 0, a1 = 0, c0q = 0, c1q = 0;
            #pragma unroll
            for (int i = 0; i < 16; i++) {
                ulonglong2 va = h0a[i]; ulonglong2 vb = h0b[i];
                fma2(a0, wA[32 + 2*i], va.x); fma2(a1, wA[33 + 2*i], va.y);
                fma2(c0q, wA[32 + 2*i], vb.x); fma2(c1q, wA[33 + 2*i], vb.y);
            }
            float ga, gb;
            if (s > 0) {
                #pragma unroll
                for (int i = 0; i < 16; i++) {
                    ulonglong2 va = h1a[i]; ulonglong2 vb = h1b[i];
                    fma2(a0, wA[2*i], va.x); fma2(a1, wA[2*i+1], va.y);
                    fma2(c0q, wA[2*i], vb.x); fma2(c1q, wA[2*i+1], vb.y);
                }
                ga = psum(a0) + psum(a1) + b0fold;
                gb = psum(c0q) + psum(c1q) + b0fold;
                // deferred FC of previous h1
                const ulonglong2* hp = (const ulonglong2*)(sH1 + bF * 64);
                unsigned long long f0 = 0, f1 = 0;
                #pragma unroll
                for (int i = 0; i < 8; i++) {
                    ulonglong2 wc0 = wfc[(2*i) * 128 + oF];
                    ulonglong2 wc1 = wfc[(2*i+1) * 128 + oF];
                    ulonglong2 h0v = hp[2*i], h1v = hp[2*i+1];
                    fma2(f0, wc0.x, h0v.x); fma2(f1, wc0.y, h0v.y);
                    fma2(f0, wc1.x, h1v.x); fma2(f1, wc1.y, h1v.y);
                }
                out[((size_t)(b0 + bF) * Tn + (s - 1)) * 128 + oF] = psum(f0) + psum(f1) + fcbO;
            } else {
                ga = psum(a0) + psum(a1) + bias0;
                gb = psum(c0q) + psum(c1q) + bias0;
            }
            sG[t] = ga; sG[256 + t] = gb;
        }
        __syncthreads();

        // P2: act0 + h1part (Whh1 blocked smem)
        float p0, p1;
        {
            const ulonglong2* h1a = (const ulonglong2*)(sH1);
            const ulonglong2* h1b = (const ulonglong2*)(sH1 + 64);
            unsigned long long q00 = 0, q01 = 0, q10 = 0, q11 = 0;
            #pragma unroll
            for (int i = 0; i < 8; i++) {
                ulonglong2 w0c = whp[(2*i) * 256 + t];
                ulonglong2 w1c = whp[(2*i+1) * 256 + t];
                ulonglong2 va0 = h1a[2*i], va1 = h1a[2*i+1];
                ulonglong2 vb0 = h1b[2*i], vb1 = h1b[2*i+1];
                fma2(q00, w0c.x, va0.x); fma2(q01, w0c.y, va0.y);
                fma2(q10, w0c.x, vb0.x); fma2(q11, w0c.y, vb0.y);
                fma2(q00, w1c.x, va1.x); fma2(q01, w1c.y, va1.y);
                fma2(q10, w1c.x, vb1.x); fma2(q11, w1c.y, vb1.y);
            }
            p0 = psum(q00) + psum(q01);
            p1 = psum(q10) + psum(q11);
        }
        if (t < 128) {
            const float* gq = sG + ab * 256;
            h0w[ab * 64 + aj] = cellact(gq[aj], gq[64 + aj], gq[128 + aj], gq[192 + aj], c0);
        }
        __syncthreads();

        // P3: gates1 = Wih1@h0 (regs) + h1part
        {
            const ulonglong2* h0a = (const ulonglong2*)(h0w);
            const ulonglong2* h0b = (const ulonglong2*)(h0w + 64);
            unsigned long long q00 = 0, q01 = 0, q10 = 0, q11 = 0;
            #pragma unroll
            for (int i = 0; i < 16; i++) {
                ulonglong2 va = h0a[i]; ulonglong2 vb = h0b[i];
                fma2(q00, wC[2*i], va.x); fma2(q01, wC[2*i+1], va.y);
                fma2(q10, wC[2*i], vb.x); fma2(q11, wC[2*i+1], vb.y);
            }
            sG[t]       = psum(q00) + psum(q01) + p0 + bias1;
            sG[256 + t] = psum(q10) + psum(q11) + p1 + bias1;
        }
        __syncthreads();

        // P4: act1
        if (t < 128) {
            const float* gq = sG + ab * 256;
            sH1[ab * 64 + aj] = cellact(gq[aj], gq[64 + aj], gq[128 + aj], gq[192 + aj], c1);
        }
        __syncthreads();
    }

    // final FC for h1[T-1]
    {
        const ulonglong2* hp = (const ulonglong2*)(sH1 + bF * 64);
        unsigned long long f0 = 0, f1 = 0;
        #pragma unroll
        for (int i = 0; i < 8; i++) {
            ulonglong2 wc0 = wfc[(2*i) * 128 + oF];
            ulonglong2 wc1 = wfc[(2*i+1) * 128 + oF];
            ulonglong2 h0v = hp[2*i], h1v = hp[2*i+1];
            fma2(f0, wc0.x, h0v.x); fma2(f1, wc0.y, h0v.y);
            fma2(f0, wc1.x, h1v.x); fma2(f1, wc1.y, h1v.y);
        }
        out[((size_t)(b0 + bF) * Tn + (Tn - 1)) * 128 + oF] = psum(f0) + psum(f1) + fcbO;
    }
}

extern "C" void kernel_launch(void* const* d_in, const int* in_sizes, int n_in,
                              void* d_out, int out_size) {
    (void)in_sizes; (void)n_in; (void)out_size;
    const float* x    = (const float*)d_in[0];
    const float* eW0i = (const float*)d_in[1];
    const float* eW0h = (const float*)d_in[2];
    const float* eb0i = (const float*)d_in[3];
    const float* eb0h = (const float*)d_in[4];
    const float* eW1i = (const float*)d_in[5];
    const float* eW1h = (const float*)d_in[6];
    const float* eb1i = (const float*)d_in[7];
    const float* eb1h = (const float*)d_in[8];
    const float* dW0i = (const float*)d_in[9];
    const float* dW0h = (const float*)d_in[10];
    const float* db0i = (const float*)d_in[11];
    const float* db0h = (const float*)d_in[12];
    const float* dW1i = (const float*)d_in[13];
    const float* dW1h = (const float*)d_in[14];
    const float* db1i = (const float*)d_in[15];
    const float* db1h = (const float*)d_in[16];
    const float* fcW  = (const float*)d_in[17];
    const float* fcb  = (const float*)d_in[18];

    prep_kernel<<<64, 256>>>(dW0i, fcW);
    dim3 pgrid(256, 32);
    prep_x_kernel<<<pgrid, 256>>>(x, eW0i, eb0i, eb0h);

    cudaFuncSetAttribute(lstm_ae_kernel, cudaFuncAttributeMaxDynamicSharedMemorySize,
                         SMEM_FLOATS * (int)sizeof(float));
    lstm_ae_kernel<<<128, 256, SMEM_FLOATS * sizeof(float)>>>(
        x, eW0i, eW0h, eb0i, eb0h, eW1i, eW1h, eb1i, eb1h,
        dW0i, dW0h, db0i, db0h, dW1i, dW1h, db1i, db1h,
        fcW, fcb, (float*)d_out);
}

// round 9
// speedup vs baseline: 1.5488x; 1.0932x over previous
#include <cuda_runtime.h>
#include <cstdint>
#include <cstddef>

// LSTM autoencoder, fused persistent kernel, round 9.
// R9 = R8 encoder (2-phase, proven) + rebalanced decoder: every movable dot
// runs on the act-idle thread half, parallel to the activations:
//   P1 gates0 only | P2 act0 || p=Whh1@h1 | P3 gates1=Wih1@h0+p | P4 act1 || FC
// h1 is parity-double-buffered so P4's FC reads h1[s-1] while act1 writes h1[s].
// 128 CTAs x 256 threads; each CTA owns 2 batch elements.

#define Tn 1024

// smem float offsets
#define OFF_WA   0        // dec Whh1 blocked [16c][256g][4]
#define OFF_WB   16384    // dec FC blocked [16c][128o][4]
#define OFF_FCB  24576    // [128]
#define OFF_XW   24704    // [2][512] XW double buffer
#define OFF_H0   25728    // [2 parity][2 batch][64]
#define OFF_H1   25984    // [2 parity][2 batch][64] (encoder uses parity 0)
#define OFF_G    26240    // [1024]: gates @0..512, dec p @512..1024 (enc gates0 @512)
#define SMEM_FLOATS 27264 // 109056 bytes

__device__ __align__(16) float g_M[256 * 64];             // dec_Wih0 @ fcW
__device__ __align__(16) float g_XW[128u * 1024u * 512u]; // enc L0 x-part, bias folded

__device__ __forceinline__ void fma2(unsigned long long& acc,
                                     unsigned long long a, unsigned long long b) {
    asm("fma.rn.f32x2 %0, %1, %2, %3;" : "=l"(acc) : "l"(a), "l"(b), "l"(acc));
}
__device__ __forceinline__ float psum(unsigned long long v) {
    float lo, hi;
    asm("mov.b64 {%0, %1}, %2;" : "=f"(lo), "=f"(hi) : "l"(v));
    return lo + hi;
}
__device__ __forceinline__ float sigm_f(float v) {
    return __fdividef(1.f, 1.f + __expf(-v));
}
__device__ __forceinline__ float tanh_f(float v) {
    float a = fabsf(v);
    float e = __expf(-2.f * a);
    float r = __fdividef(1.f - e, 1.f + e);
    return v < 0.f ? -r : r;
}
__device__ __forceinline__ float cellact(float gi, float gf, float gg, float go, float& c) {
    c = sigm_f(gf) * c + sigm_f(gi) * tanh_f(gg);
    return sigm_f(go) * tanh_f(c);
}

__global__ void prep_kernel(const float* __restrict__ dW0i, const float* __restrict__ fcW) {
    int id = blockIdx.x * blockDim.x + threadIdx.x;  // 0..16383
    int g = id >> 6, j = id & 63;
    float acc = 0.f;
    #pragma unroll 4
    for (int d = 0; d < 128; d++)
        acc = fmaf(dW0i[g * 128 + d], fcW[d * 64 + j], acc);
    g_M[id] = acc;
}

// XW[pair][s][e][g] = x[b,s,:] . Wih0[g,:] + eb0i[g] + eb0h[g]
__global__ void __launch_bounds__(256, 1)
prep_x_kernel(const float* __restrict__ x, const float* __restrict__ eW0i,
              const float* __restrict__ eb0i, const float* __restrict__ eb0h) {
    __shared__ float sx[32 * 128];
    const int b  = blockIdx.x;     // 0..255
    const int ch = blockIdx.y;     // 0..31
    const int t  = threadIdx.x;    // gate 0..255

    for (int i = t; i < 32 * 128; i += 256)
        sx[i] = x[((size_t)b * Tn + ch * 32) * 128 + i];

    unsigned long long w[64];
    const ulonglong2* p = (const ulonglong2*)(eW0i + t * 128);
    #pragma unroll
    for (int i = 0; i < 32; i++) { ulonglong2 v = p[i]; w[2*i] = v.x; w[2*i+1] = v.y; }
    const float bias = eb0i[t] + eb0h[t];
    __syncthreads();

    for (int s = 0; s < 32; s++) {
        const ulonglong2* xp = (const ulonglong2*)(sx + s * 128);
        unsigned long long q0 = 0ull, q1 = 0ull;
        #pragma unroll
        for (int i = 0; i < 32; i++) {
            ulonglong2 v = xp[i];
            fma2(q0, w[2*i], v.x);
            fma2(q1, w[2*i+1], v.y);
        }
        g_XW[(((size_t)(b >> 1) * Tn + ch * 32 + s) * 2 + (b & 1)) * 256 + t] =
            psum(q0) + psum(q1) + bias;
    }
}

__global__ void __launch_bounds__(256, 1)
lstm_ae_kernel(const float* __restrict__ x,
               const float* __restrict__ eW0i, const float* __restrict__ eW0h,
               const float* __restrict__ eb0i, const float* __restrict__ eb0h,
               const float* __restrict__ eW1i, const float* __restrict__ eW1h,
               const float* __restrict__ eb1i, const float* __restrict__ eb1h,
               const float* __restrict__ dW0i, const float* __restrict__ dW0h,
               const float* __restrict__ db0i, const float* __restrict__ db0h,
               const float* __restrict__ dW1i, const float* __restrict__ dW1h,
               const float* __restrict__ db1i, const float* __restrict__ db1h,
               const float* __restrict__ fcW,  const float* __restrict__ fcb,
               float* __restrict__ out)
{
    extern __shared__ float sm[];
    float* sWA  = sm + OFF_WA;
    float* sWB  = sm + OFF_WB;
    float* sFCb = sm + OFF_FCB;
    float* sXW  = sm + OFF_XW;
    float* sH0  = sm + OFF_H0;
    float* sH1  = sm + OFF_H1;
    float* sG   = sm + OFF_G;

    const int t  = threadIdx.x;
    const int b0 = blockIdx.x * 2;
    const int aj = t & 63;
    const int ab = (t >> 6) & 1;

    float c0 = 0.f, c1 = 0.f;

    // ---- stage decoder smem weights up front ----
    for (int idx = t; idx < 256 * 64; idx += 256) {
        int g = idx >> 6, k = idx & 63;
        sWA[(k >> 2) * 1024 + g * 4 + (k & 3)] = dW1h[idx];
    }
    for (int idx = t; idx < 128 * 64; idx += 256) {
        int o = idx >> 6, k = idx & 63;
        sWB[(k >> 2) * 512 + o * 4 + (k & 3)] = fcW[idx];
    }
    if (t < 128) { sFCb[t] = fcb[t]; sH1[t] = 0.f; }

    // ================= ENCODER (R8-verbatim, 2 phases/step) =================
    {
        unsigned long long wH0[32], wI1[32], wH1[32];   // rows t of Whh0, Wih1, Whh1
        {
            const ulonglong2* p = (const ulonglong2*)(eW0h + t * 64);
            #pragma unroll
            for (int i = 0; i < 16; i++) { ulonglong2 v = p[i]; wH0[2*i] = v.x; wH0[2*i+1] = v.y; }
            const ulonglong2* q = (const ulonglong2*)(eW1i + t * 64);
            #pragma unroll
            for (int i = 0; i < 16; i++) { ulonglong2 v = q[i]; wI1[2*i] = v.x; wI1[2*i+1] = v.y; }
            const ulonglong2* r = (const ulonglong2*)(eW1h + t * 64);
            #pragma unroll
            for (int i = 0; i < 16; i++) { ulonglong2 v = r[i]; wH1[2*i] = v.x; wH1[2*i+1] = v.y; }
        }
        const float bias1 = eb1i[t] + eb1h[t];
        const size_t xwbase = (size_t)blockIdx.x * Tn * 512;

        // prologue: XW[0] -> slot0; gates0[0]; act0[0]; prefetch XW[1],XW[2]
        if (t < 128) {
            const float* src = g_XW + xwbase + t * 4;
            uint32_t dst = (uint32_t)__cvta_generic_to_shared(sXW + t * 4);
            asm volatile("cp.async.cg.shared.global [%0], [%1], 16;" :: "r"(dst), "l"(src) : "memory");
        }
        asm volatile("cp.async.commit_group;" ::: "memory");
        asm volatile("cp.async.wait_group 0;" ::: "memory");
        __syncthreads();

        sG[512 + t] = sXW[t];          // gates0[0] = XW[0] (h0[-1]=0)
        sG[768 + t] = sXW[256 + t];
        __syncthreads();

        if (t >= 128) {                // act0[0] -> h0[0]
            int t2 = t - 128, aB = (t2 >> 6) & 1, aj2 = t2 & 63;
            const float* gq = sG + 512 + aB * 256;
            sH0[aB * 64 + aj2] = cellact(gq[aj2], gq[64 + aj2], gq[128 + aj2], gq[192 + aj2], c0);
        } else {                       // prefetch XW[1] -> slot1
            const float* src = g_XW + xwbase + (size_t)1 * 512 + t * 4;
            uint32_t dst = (uint32_t)__cvta_generic_to_shared(sXW + 512 + t * 4);
            asm volatile("cp.async.cg.shared.global [%0], [%1], 16;" :: "r"(dst), "l"(src) : "memory");
        }
        asm volatile("cp.async.commit_group;" ::: "memory");
        if (t < 128) {                 // prefetch XW[2] -> slot0
            const float* src = g_XW + xwbase + (size_t)2 * 512 + t * 4;
            uint32_t dst = (uint32_t)__cvta_generic_to_shared(sXW + t * 4);
            asm volatile("cp.async.cg.shared.global [%0], [%1], 16;" :: "r"(dst), "l"(src) : "memory");
        }
        asm volatile("cp.async.commit_group;" ::: "memory");
        __syncthreads();

        for (int s = 0; s < Tn; s++) {
            asm volatile("cp.async.wait_group 1;" ::: "memory");  // XW[s+1] landed
            {
                const float* xw = sXW + ((s + 1) & 1) * 512;
                const ulonglong2* h0a = (const ulonglong2*)(sH0);
                const ulonglong2* h0b = (const ulonglong2*)(sH0 + 64);
                const ulonglong2* h1a = (const ulonglong2*)(sH1);
                const ulonglong2* h1b = (const ulonglong2*)(sH1 + 64);
                unsigned long long qa0 = 0, qa1 = 0, qb0 = 0, qb1 = 0;   // Wih1@h0
                unsigned long long ra0 = 0, ra1 = 0, rb0 = 0, rb1 = 0;   // Whh1@h1
                unsigned long long sa0 = 0, sa1 = 0, sb0 = 0, sb1 = 0;   // Whh0@h0
                #pragma unroll
                for (int i = 0; i < 16; i++) {
                    ulonglong2 va = h0a[i], vb = h0b[i];
                    fma2(qa0, wI1[2*i], va.x); fma2(qa1, wI1[2*i+1], va.y);
                    fma2(qb0, wI1[2*i], vb.x); fma2(qb1, wI1[2*i+1], vb.y);
                    fma2(sa0, wH0[2*i], va.x); fma2(sa1, wH0[2*i+1], va.y);
                    fma2(sb0, wH0[2*i], vb.x); fma2(sb1, wH0[2*i+1], vb.y);
                    ulonglong2 wa = h1a[i], wb = h1b[i];
                    fma2(ra0, wH1[2*i], wa.x); fma2(ra1, wH1[2*i+1], wa.y);
                    fma2(rb0, wH1[2*i], wb.x); fma2(rb1, wH1[2*i+1], wb.y);
                }
                sG[t]       = psum(qa0) + psum(qa1) + psum(ra0) + psum(ra1) + bias1;
                sG[256 + t] = psum(qb0) + psum(qb1) + psum(rb0) + psum(rb1) + bias1;
                sG[512 + t] = xw[t]       + psum(sa0) + psum(sa1);
                sG[768 + t] = xw[256 + t] + psum(sb0) + psum(sb1);
            }
            __syncthreads();

            if (t < 128) {
                const float* gq = sG + ab * 256;
                sH1[ab * 64 + aj] = cellact(gq[aj], gq[64 + aj], gq[128 + aj], gq[192 + aj], c1);
            } else {
                if (s + 1 < Tn) {
                    int t2 = t - 128, aB = (t2 >> 6) & 1, aj2 = t2 & 63;
                    const float* gq = sG + 512 + aB * 256;
                    sH0[aB * 64 + aj2] = cellact(gq[aj2], gq[64 + aj2], gq[128 + aj2], gq[192 + aj2], c0);
                }
                if (s + 3 < Tn) {
                    int l = t - 128;
                    const float* src = g_XW + xwbase + (size_t)(s + 3) * 512 + l * 4;
                    uint32_t dst = (uint32_t)__cvta_generic_to_shared(sXW + ((s + 1) & 1) * 512 + l * 4);
                    asm volatile("cp.async.cg.shared.global [%0], [%1], 16;" :: "r"(dst), "l"(src) : "memory");
                }
            }
            asm volatile("cp.async.commit_group;" ::: "memory");
            __syncthreads();
        }
        asm volatile("cp.async.wait_group 0;" ::: "memory");
    }

    // ================= TRANSITION =================
    if (t >= 128) sG[t - 128] = c0;   // hand off c0 to t<128 (same (ab,aj) map)
    __syncthreads();
    if (t < 128) {
        c0 = tanh_f(sG[t]);
        c1 = tanh_f(c1);
        sH0[t] = tanh_f(sH0[t]);   // h0[T-1] -> decoder parity buffer 0
        sH1[t] = tanh_f(sH1[t]);   // h1[T-1] -> decoder parity buffer 0
    }
    unsigned long long wA[64];  // [0..31] M row (over h1), [32..63] Whh0 row (over h0)
    unsigned long long wC[32];  // Wih1 row (over h0)
    {
        const ulonglong2* p = (const ulonglong2*)(g_M + t * 64);
        #pragma unroll
        for (int i = 0; i < 16; i++) { ulonglong2 v = p[i]; wA[2*i] = v.x; wA[2*i+1] = v.y; }
        const ulonglong2* q = (const ulonglong2*)(dW0h + t * 64);
        #pragma unroll
        for (int i = 0; i < 16; i++) { ulonglong2 v = q[i]; wA[32+2*i] = v.x; wA[33+2*i] = v.y; }
        const ulonglong2* r = (const ulonglong2*)(dW1i + t * 64);
        #pragma unroll
        for (int i = 0; i < 16; i++) { ulonglong2 v = r[i]; wC[2*i] = v.x; wC[2*i+1] = v.y; }
    }
    const float bias0 = db0i[t] + db0h[t];
    float b0fold;
    {
        float a = 0.f;
        #pragma unroll 4
        for (int d = 0; d < 128; d++) a = fmaf(dW0i[t * 128 + d], fcb[d], a);
        b0fold = bias0 + a;   // bias0 + Wih0 @ fcb
    }
    const float bias1 = db1i[t] + db1h[t];
    __syncthreads();

    // ================= DECODER (rebalanced, 4 short phases/step) =================
    const int u = t - 128;                            // t>=128 helper id 0..127
    const ulonglong2* whp = (const ulonglong2*)sWA;   // Whh1 blocked [c*256 + g]
    const ulonglong2* wfc = (const ulonglong2*)sWB;   // FC blocked  [c*128 + o]

    for (int s = 0; s < Tn; s++) {
        const int par = s & 1;
        const float* h0r = sH0 + par * 128;
        float*       h0w = sH0 + (par ^ 1) * 128;
        const float* h1r = sH1 + par * 128;
        float*       h1w = sH1 + (par ^ 1) * 128;

        // ---- P1: gates0 only (all threads) ----
        {
            const ulonglong2* h0a = (const ulonglong2*)(h0r);
            const ulonglong2* h0b = (const ulonglong2*)(h0r + 64);
            unsigned long long a0 = 0, a1 = 0, c0q = 0, c1q = 0;
            #pragma unroll
            for (int i = 0; i < 16; i++) {
                ulonglong2 va = h0a[i]; ulonglong2 vb = h0b[i];
                fma2(a0, wA[32 + 2*i], va.x); fma2(a1, wA[33 + 2*i], va.y);
                fma2(c0q, wA[32 + 2*i], vb.x); fma2(c1q, wA[33 + 2*i], vb.y);
            }
            float ga, gb;
            if (s > 0) {
                const ulonglong2* h1a = (const ulonglong2*)(h1r);
                const ulonglong2* h1b = (const ulonglong2*)(h1r + 64);
                #pragma unroll
                for (int i = 0; i < 16; i++) {
                    ulonglong2 va = h1a[i]; ulonglong2 vb = h1b[i];
                    fma2(a0, wA[2*i], va.x); fma2(a1, wA[2*i+1], va.y);
                    fma2(c0q, wA[2*i], vb.x); fma2(c1q, wA[2*i+1], vb.y);
                }
                ga = psum(a0) + psum(a1) + b0fold;
                gb = psum(c0q) + psum(c1q) + b0fold;
            } else {
                ga = psum(a0) + psum(a1) + bias0;
                gb = psum(c0q) + psum(c1q) + bias0;
            }
            sG[t] = ga; sG[256 + t] = gb;
        }
        __syncthreads();

        // ---- P2: act0 (t<128) || p = Whh1@h1[s-1] for gates u, u+128 (t>=128) ----
        if (t < 128) {
            const float* gq = sG + ab * 256;
            h0w[ab * 64 + aj] = cellact(gq[aj], gq[64 + aj], gq[128 + aj], gq[192 + aj], c0);
        } else {
            const ulonglong2* h1a = (const ulonglong2*)(h1r);
            const ulonglong2* h1b = (const ulonglong2*)(h1r + 64);
            unsigned long long pA0 = 0, pA1 = 0, pB0 = 0, pB1 = 0;
            #pragma unroll
            for (int c = 0; c < 16; c++) {
                ulonglong2 w1 = whp[c * 256 + u];
                ulonglong2 w2 = whp[c * 256 + u + 128];
                ulonglong2 hA = h1a[c], hB = h1b[c];
                fma2(pA0, w1.x, hA.x); fma2(pA0, w1.y, hA.y);
                fma2(pA1, w1.x, hB.x); fma2(pA1, w1.y, hB.y);
                fma2(pB0, w2.x, hA.x); fma2(pB0, w2.y, hA.y);
                fma2(pB1, w2.x, hB.x); fma2(pB1, w2.y, hB.y);
            }
            sG[512 + u]       = psum(pA0);   // gate u,     b0
            sG[768 + u]       = psum(pA1);   // gate u,     b1
            sG[512 + u + 128] = psum(pB0);   // gate u+128, b0
            sG[768 + u + 128] = psum(pB1);   // gate u+128, b1
        }
        __syncthreads();

        // ---- P3: gates1 = Wih1@h0[s] (regs) + p + bias1 (all threads) ----
        {
            const ulonglong2* h0a = (const ulonglong2*)(h0w);
            const ulonglong2* h0b = (const ulonglong2*)(h0w + 64);
            unsigned long long q00 = 0, q01 = 0, q10 = 0, q11 = 0;
            #pragma unroll
            for (int i = 0; i < 16; i++) {
                ulonglong2 va = h0a[i]; ulonglong2 vb = h0b[i];
                fma2(q00, wC[2*i], va.x); fma2(q01, wC[2*i+1], va.y);
                fma2(q10, wC[2*i], vb.x); fma2(q11, wC[2*i+1], vb.y);
            }
            sG[t]       = psum(q00) + psum(q01) + sG[512 + t] + bias1;
            sG[256 + t] = psum(q10) + psum(q11) + sG[768 + t] + bias1;
        }
        __syncthreads();

        // ---- P4: act1 (t<128) || FC(h1[s-1]) -> out[s-1] (t>=128, s>0) ----
        if (t < 128) {
            const float* gq = sG + ab * 256;
            h1w[ab * 64 + aj] = cellact(gq[aj], gq[64 + aj], gq[128 + aj], gq[192 + aj], c1);
        } else if (s > 0) {
            const ulonglong2* hA = (const ulonglong2*)(h1r);
            const ulonglong2* hB = (const ulonglong2*)(h1r + 64);
            unsigned long long fA0 = 0, fA1 = 0, fB0 = 0, fB1 = 0;
            #pragma unroll
            for (int c = 0; c < 16; c += 2) {
                ulonglong2 w0c = wfc[c * 128 + u];
                ulonglong2 w1c = wfc[(c + 1) * 128 + u];
                ulonglong2 a0v = hA[c], a1v = hA[c + 1];
                ulonglong2 b0v = hB[c], b1v = hB[c + 1];
                fma2(fA0, w0c.x, a0v.x); fma2(fA1, w0c.y, a0v.y);
                fma2(fA0, w1c.x, a1v.x); fma2(fA1, w1c.y, a1v.y);
                fma2(fB0, w0c.x, b0v.x); fma2(fB1, w0c.y, b0v.y);
                fma2(fB0, w1c.x, b1v.x); fma2(fB1, w1c.y, b1v.y);
            }
            float prA = psum(fA0) + psum(fA1) + sFCb[u];
            float prB = psum(fB0) + psum(fB1) + sFCb[u];
            out[((size_t)(b0 + 0) * Tn + (s - 1)) * 128 + u] = prA;
            out[((size_t)(b0 + 1) * Tn + (s - 1)) * 128 + u] = prB;
        }
        __syncthreads();
    }

    // final FC for h1[T-1] (in parity buffer 0 after s=1023)
    if (t >= 128) {
        const float* h1f = sH1;   // parity (Tn & 1) = 0
        const ulonglong2* hA = (const ulonglong2*)(h1f);
        const ulonglong2* hB = (const ulonglong2*)(h1f + 64);
        unsigned long long fA0 = 0, fA1 = 0, fB0 = 0, fB1 = 0;
        #pragma unroll
        for (int c = 0; c < 16; c += 2) {
            ulonglong2 w0c = wfc[c * 128 + u];
            ulonglong2 w1c = wfc[(c + 1) * 128 + u];
            ulonglong2 a0v = hA[c], a1v = hA[c + 1];
            ulonglong2 b0v = hB[c], b1v = hB[c + 1];
            fma2(fA0, w0c.x, a0v.x); fma2(fA1, w0c.y, a0v.y);
            fma2(fA0, w1c.x, a1v.x); fma2(fA1, w1c.y, a1v.y);
            fma2(fB0, w0c.x, b0v.x); fma2(fB1, w0c.y, b0v.y);
            fma2(fB0, w1c.x, b1v.x); fma2(fB1, w1c.y, b1v.y);
        }
        out[((size_t)(b0 + 0) * Tn + (Tn - 1)) * 128 + u] = psum(fA0) + psum(fA1) + sFCb[u];
        out[((size_t)(b0 + 1) * Tn + (Tn - 1)) * 128 + u] = psum(fB0) + psum(fB1) + sFCb[u];
    }
}

extern "C" void kernel_launch(void* const* d_in, const int* in_sizes, int n_in,
                              void* d_out, int out_size) {
    (void)in_sizes; (void)n_in; (void)out_size;
    const float* x    = (const float*)d_in[0];
    const float* eW0i = (const float*)d_in[1];
    const float* eW0h = (const float*)d_in[2];
    const float* eb0i = (const float*)d_in[3];
    const float* eb0h = (const float*)d_in[4];
    const float* eW1i = (const float*)d_in[5];
    const float* eW1h = (const float*)d_in[6];
    const float* eb1i = (const float*)d_in[7];
    const float* eb1h = (const float*)d_in[8];
    const float* dW0i = (const float*)d_in[9];
    const float* dW0h = (const float*)d_in[10];
    const float* db0i = (const float*)d_in[11];
    const float* db0h = (const float*)d_in[12];
    const float* dW1i = (const float*)d_in[13];
    const float* dW1h = (const float*)d_in[14];
    const float* db1i = (const float*)d_in[15];
    const float* db1h = (const float*)d_in[16];
    const float* fcW  = (const float*)d_in[17];
    const float* fcb  = (const float*)d_in[18];

    prep_kernel<<<64, 256>>>(dW0i, fcW);
    dim3 pgrid(256, 32);
    prep_x_kernel<<<pgrid, 256>>>(x, eW0i, eb0i, eb0h);

    cudaFuncSetAttribute(lstm_ae_kernel, cudaFuncAttributeMaxDynamicSharedMemorySize,
                         SMEM_FLOATS * (int)sizeof(float));
    lstm_ae_kernel<<<128, 256, SMEM_FLOATS * sizeof(float)>>>(
        x, eW0i, eW0h, eb0i, eb0h, eW1i, eW1h, eb1i, eb1h,
        dW0i, dW0h, db0i, db0h, dW1i, dW1h, db1i, db1h,
        fcW, fcb, (float*)d_out);
}

// round 10
// speedup vs baseline: 1.5820x; 1.0214x over previous
#include <cuda_runtime.h>
#include <cstdint>
#include <cstddef>

// LSTM autoencoder, fused persistent kernel, round 10.
// R10 = R9 encoder (2-phase) + decoder re-packed for h1-load reuse:
//   P1 gates0 + p=Whh1@h1[s-1] (shares h1 loads; p kept in registers)
//   P2 act0 || FC(h1[s-1]) -> out[s-1]
//   P3 gates1 = Wih1@h0[s] + p
//   P4 act1
// 128 CTAs x 256 threads; each CTA owns 2 batch elements.

#define Tn 1024

// smem float offsets
#define OFF_WA   0        // dec Whh1 blocked [16c][256g][4]
#define OFF_WB   16384    // dec FC blocked [16c][128o][4]
#define OFF_FCB  24576    // [128]
#define OFF_XW   24704    // [2][512] XW double buffer
#define OFF_H0   25728    // [2 parity][2 batch][64]
#define OFF_H1   25984    // [2 parity][2 batch][64] (encoder uses parity 0)
#define OFF_G    26240    // [1024]: gates @0..512 (enc gates0 @512)
#define SMEM_FLOATS 27264 // 109056 bytes

__device__ __align__(16) float g_M[256 * 64];             // dec_Wih0 @ fcW
__device__ __align__(16) float g_XW[128u * 1024u * 512u]; // enc L0 x-part, bias folded

__device__ __forceinline__ void fma2(unsigned long long& acc,
                                     unsigned long long a, unsigned long long b) {
    asm("fma.rn.f32x2 %0, %1, %2, %3;" : "=l"(acc) : "l"(a), "l"(b), "l"(acc));
}
__device__ __forceinline__ float psum(unsigned long long v) {
    float lo, hi;
    asm("mov.b64 {%0, %1}, %2;" : "=f"(lo), "=f"(hi) : "l"(v));
    return lo + hi;
}
__device__ __forceinline__ float sigm_f(float v) {
    return __fdividef(1.f, 1.f + __expf(-v));
}
__device__ __forceinline__ float tanh_f(float v) {
    float a = fabsf(v);
    float e = __expf(-2.f * a);
    float r = __fdividef(1.f - e, 1.f + e);
    return v < 0.f ? -r : r;
}
__device__ __forceinline__ float cellact(float gi, float gf, float gg, float go, float& c) {
    c = sigm_f(gf) * c + sigm_f(gi) * tanh_f(gg);
    return sigm_f(go) * tanh_f(c);
}

__global__ void prep_kernel(const float* __restrict__ dW0i, const float* __restrict__ fcW) {
    int id = blockIdx.x * blockDim.x + threadIdx.x;  // 0..16383
    int g = id >> 6, j = id & 63;
    float acc = 0.f;
    #pragma unroll 4
    for (int d = 0; d < 128; d++)
        acc = fmaf(dW0i[g * 128 + d], fcW[d * 64 + j], acc);
    g_M[id] = acc;
}

// XW[pair][s][e][g] = x[b,s,:] . Wih0[g,:] + eb0i[g] + eb0h[g]
__global__ void __launch_bounds__(256, 1)
prep_x_kernel(const float* __restrict__ x, const float* __restrict__ eW0i,
              const float* __restrict__ eb0i, const float* __restrict__ eb0h) {
    __shared__ float sx[32 * 128];
    const int b  = blockIdx.x;     // 0..255
    const int ch = blockIdx.y;     // 0..31
    const int t  = threadIdx.x;    // gate 0..255

    for (int i = t; i < 32 * 128; i += 256)
        sx[i] = x[((size_t)b * Tn + ch * 32) * 128 + i];

    unsigned long long w[64];
    const ulonglong2* p = (const ulonglong2*)(eW0i + t * 128);
    #pragma unroll
    for (int i = 0; i < 32; i++) { ulonglong2 v = p[i]; w[2*i] = v.x; w[2*i+1] = v.y; }
    const float bias = eb0i[t] + eb0h[t];
    __syncthreads();

    for (int s = 0; s < 32; s++) {
        const ulonglong2* xp = (const ulonglong2*)(sx + s * 128);
        unsigned long long q0 = 0ull, q1 = 0ull;
        #pragma unroll
        for (int i = 0; i < 32; i++) {
            ulonglong2 v = xp[i];
            fma2(q0, w[2*i], v.x);
            fma2(q1, w[2*i+1], v.y);
        }
        g_XW[(((size_t)(b >> 1) * Tn + ch * 32 + s) * 2 + (b & 1)) * 256 + t] =
            psum(q0) + psum(q1) + bias;
    }
}

__global__ void __launch_bounds__(256, 1)
lstm_ae_kernel(const float* __restrict__ x,
               const float* __restrict__ eW0i, const float* __restrict__ eW0h,
               const float* __restrict__ eb0i, const float* __restrict__ eb0h,
               const float* __restrict__ eW1i, const float* __restrict__ eW1h,
               const float* __restrict__ eb1i, const float* __restrict__ eb1h,
               const float* __restrict__ dW0i, const float* __restrict__ dW0h,
               const float* __restrict__ db0i, const float* __restrict__ db0h,
               const float* __restrict__ dW1i, const float* __restrict__ dW1h,
               const float* __restrict__ db1i, const float* __restrict__ db1h,
               const float* __restrict__ fcW,  const float* __restrict__ fcb,
               float* __restrict__ out)
{
    extern __shared__ float sm[];
    float* sWA  = sm + OFF_WA;
    float* sWB  = sm + OFF_WB;
    float* sFCb = sm + OFF_FCB;
    float* sXW  = sm + OFF_XW;
    float* sH0  = sm + OFF_H0;
    float* sH1  = sm + OFF_H1;
    float* sG   = sm + OFF_G;

    const int t  = threadIdx.x;
    const int b0 = blockIdx.x * 2;
    const int aj = t & 63;
    const int ab = (t >> 6) & 1;

    float c0 = 0.f, c1 = 0.f;

    // ---- stage decoder smem weights up front ----
    for (int idx = t; idx < 256 * 64; idx += 256) {
        int g = idx >> 6, k = idx & 63;
        sWA[(k >> 2) * 1024 + g * 4 + (k & 3)] = dW1h[idx];
    }
    for (int idx = t; idx < 128 * 64; idx += 256) {
        int o = idx >> 6, k = idx & 63;
        sWB[(k >> 2) * 512 + o * 4 + (k & 3)] = fcW[idx];
    }
    if (t < 128) { sFCb[t] = fcb[t]; sH1[t] = 0.f; }

    // ================= ENCODER (R8-verbatim, 2 phases/step) =================
    {
        unsigned long long wH0[32], wI1[32], wH1[32];   // rows t of Whh0, Wih1, Whh1
        {
            const ulonglong2* p = (const ulonglong2*)(eW0h + t * 64);
            #pragma unroll
            for (int i = 0; i < 16; i++) { ulonglong2 v = p[i]; wH0[2*i] = v.x; wH0[2*i+1] = v.y; }
            const ulonglong2* q = (const ulonglong2*)(eW1i + t * 64);
            #pragma unroll
            for (int i = 0; i < 16; i++) { ulonglong2 v = q[i]; wI1[2*i] = v.x; wI1[2*i+1] = v.y; }
            const ulonglong2* r = (const ulonglong2*)(eW1h + t * 64);
            #pragma unroll
            for (int i = 0; i < 16; i++) { ulonglong2 v = r[i]; wH1[2*i] = v.x; wH1[2*i+1] = v.y; }
        }
        const float bias1 = eb1i[t] + eb1h[t];
        const size_t xwbase = (size_t)blockIdx.x * Tn * 512;

        // prologue: XW[0] -> slot0; gates0[0]; act0[0]; prefetch XW[1],XW[2]
        if (t < 128) {
            const float* src = g_XW + xwbase + t * 4;
            uint32_t dst = (uint32_t)__cvta_generic_to_shared(sXW + t * 4);
            asm volatile("cp.async.cg.shared.global [%0], [%1], 16;" :: "r"(dst), "l"(src) : "memory");
        }
        asm volatile("cp.async.commit_group;" ::: "memory");
        asm volatile("cp.async.wait_group 0;" ::: "memory");
        __syncthreads();

        sG[512 + t] = sXW[t];          // gates0[0] = XW[0] (h0[-1]=0)
        sG[768 + t] = sXW[256 + t];
        __syncthreads();

        if (t >= 128) {                // act0[0] -> h0[0]
            int t2 = t - 128, aB = (t2 >> 6) & 1, aj2 = t2 & 63;
            const float* gq = sG + 512 + aB * 256;
            sH0[aB * 64 + aj2] = cellact(gq[aj2], gq[64 + aj2], gq[128 + aj2], gq[192 + aj2], c0);
        } else {                       // prefetch XW[1] -> slot1
            const float* src = g_XW + xwbase + (size_t)1 * 512 + t * 4;
            uint32_t dst = (uint32_t)__cvta_generic_to_shared(sXW + 512 + t * 4);
            asm volatile("cp.async.cg.shared.global [%0], [%1], 16;" :: "r"(dst), "l"(src) : "memory");
        }
        asm volatile("cp.async.commit_group;" ::: "memory");
        if (t < 128) {                 // prefetch XW[2] -> slot0
            const float* src = g_XW + xwbase + (size_t)2 * 512 + t * 4;
            uint32_t dst = (uint32_t)__cvta_generic_to_shared(sXW + t * 4);
            asm volatile("cp.async.cg.shared.global [%0], [%1], 16;" :: "r"(dst), "l"(src) : "memory");
        }
        asm volatile("cp.async.commit_group;" ::: "memory");
        __syncthreads();

        for (int s = 0; s < Tn; s++) {
            asm volatile("cp.async.wait_group 1;" ::: "memory");  // XW[s+1] landed
            {
                const float* xw = sXW + ((s + 1) & 1) * 512;
                const ulonglong2* h0a = (const ulonglong2*)(sH0);
                const ulonglong2* h0b = (const ulonglong2*)(sH0 + 64);
                const ulonglong2* h1a = (const ulonglong2*)(sH1);
                const ulonglong2* h1b = (const ulonglong2*)(sH1 + 64);
                unsigned long long qa0 = 0, qa1 = 0, qb0 = 0, qb1 = 0;   // Wih1@h0
                unsigned long long ra0 = 0, ra1 = 0, rb0 = 0, rb1 = 0;   // Whh1@h1
                unsigned long long sa0 = 0, sa1 = 0, sb0 = 0, sb1 = 0;   // Whh0@h0
                #pragma unroll
                for (int i = 0; i < 16; i++) {
                    ulonglong2 va = h0a[i], vb = h0b[i];
                    fma2(qa0, wI1[2*i], va.x); fma2(qa1, wI1[2*i+1], va.y);
                    fma2(qb0, wI1[2*i], vb.x); fma2(qb1, wI1[2*i+1], vb.y);
                    fma2(sa0, wH0[2*i], va.x); fma2(sa1, wH0[2*i+1], va.y);
                    fma2(sb0, wH0[2*i], vb.x); fma2(sb1, wH0[2*i+1], vb.y);
                    ulonglong2 wa = h1a[i], wb = h1b[i];
                    fma2(ra0, wH1[2*i], wa.x); fma2(ra1, wH1[2*i+1], wa.y);
                    fma2(rb0, wH1[2*i], wb.x); fma2(rb1, wH1[2*i+1], wb.y);
                }
                sG[t]       = psum(qa0) + psum(qa1) + psum(ra0) + psum(ra1) + bias1;
                sG[256 + t] = psum(qb0) + psum(qb1) + psum(rb0) + psum(rb1) + bias1;
                sG[512 + t] = xw[t]       + psum(sa0) + psum(sa1);
                sG[768 + t] = xw[256 + t] + psum(sb0) + psum(sb1);
            }
            __syncthreads();

            if (t < 128) {
                const float* gq = sG + ab * 256;
                sH1[ab * 64 + aj] = cellact(gq[aj], gq[64 + aj], gq[128 + aj], gq[192 + aj], c1);
            } else {
                if (s + 1 < Tn) {
                    int t2 = t - 128, aB = (t2 >> 6) & 1, aj2 = t2 & 63;
                    const float* gq = sG + 512 + aB * 256;
                    sH0[aB * 64 + aj2] = cellact(gq[aj2], gq[64 + aj2], gq[128 + aj2], gq[192 + aj2], c0);
                }
                if (s + 3 < Tn) {
                    int l = t - 128;
                    const float* src = g_XW + xwbase + (size_t)(s + 3) * 512 + l * 4;
                    uint32_t dst = (uint32_t)__cvta_generic_to_shared(sXW + ((s + 1) & 1) * 512 + l * 4);
                    asm volatile("cp.async.cg.shared.global [%0], [%1], 16;" :: "r"(dst), "l"(src) : "memory");
                }
            }
            asm volatile("cp.async.commit_group;" ::: "memory");
            __syncthreads();
        }
        asm volatile("cp.async.wait_group 0;" ::: "memory");
    }

    // ================= TRANSITION =================
    if (t >= 128) sG[t - 128] = c0;   // hand off c0 to t<128 (same (ab,aj) map)
    __syncthreads();
    if (t < 128) {
        c0 = tanh_f(sG[t]);
        c1 = tanh_f(c1);
        sH0[t] = tanh_f(sH0[t]);   // h0[T-1] -> decoder parity buffer 0
        sH1[t] = tanh_f(sH1[t]);   // h1[T-1] -> decoder parity buffer 0
    }
    unsigned long long wA[64];  // [0..31] M row (over h1), [32..63] Whh0 row (over h0)
    unsigned long long wC[32];  // Wih1 row (over h0)
    {
        const ulonglong2* p = (const ulonglong2*)(g_M + t * 64);
        #pragma unroll
        for (int i = 0; i < 16; i++) { ulonglong2 v = p[i]; wA[2*i] = v.x; wA[2*i+1] = v.y; }
        const ulonglong2* q = (const ulonglong2*)(dW0h + t * 64);
        #pragma unroll
        for (int i = 0; i < 16; i++) { ulonglong2 v = q[i]; wA[32+2*i] = v.x; wA[33+2*i] = v.y; }
        const ulonglong2* r = (const ulonglong2*)(dW1i + t * 64);
        #pragma unroll
        for (int i = 0; i < 16; i++) { ulonglong2 v = r[i]; wC[2*i] = v.x; wC[2*i+1] = v.y; }
    }
    const float bias0 = db0i[t] + db0h[t];
    float b0fold;
    {
        float a = 0.f;
        #pragma unroll 4
        for (int d = 0; d < 128; d++) a = fmaf(dW0i[t * 128 + d], fcb[d], a);
        b0fold = bias0 + a;   // bias0 + Wih0 @ fcb
    }
    const float bias1 = db1i[t] + db1h[t];
    __syncthreads();

    // ================= DECODER (4 phases, h1-load reuse) =================
    const int u = t - 128;                            // t>=128 helper id 0..127
    const ulonglong2* whp = (const ulonglong2*)sWA;   // Whh1 blocked [c*256 + g]
    const ulonglong2* wfc = (const ulonglong2*)sWB;   // FC blocked  [c*128 + o]

    for (int s = 0; s < Tn; s++) {
        const int par = s & 1;
        const float* h0r = sH0 + par * 128;
        float*       h0w = sH0 + (par ^ 1) * 128;
        const float* h1r = sH1 + par * 128;
        float*       h1w = sH1 + (par ^ 1) * 128;

        // ---- P1: gates0 + p = Whh1@h1[s-1] (shares h1 loads; p kept in regs) ----
        float p0, p1;
        {
            const ulonglong2* h0a = (const ulonglong2*)(h0r);
            const ulonglong2* h0b = (const ulonglong2*)(h0r + 64);
            const ulonglong2* h1a = (const ulonglong2*)(h1r);
            const ulonglong2* h1b = (const ulonglong2*)(h1r + 64);

            unsigned long long a0 = 0, a1 = 0, c0q = 0, c1q = 0;       // gates0
            unsigned long long q00 = 0, q01 = 0, q10 = 0, q11 = 0;     // p
            #pragma unroll
            for (int i = 0; i < 16; i++) {
                ulonglong2 va = h0a[i]; ulonglong2 vb = h0b[i];
                fma2(a0, wA[32 + 2*i], va.x); fma2(a1, wA[33 + 2*i], va.y);
                fma2(c0q, wA[32 + 2*i], vb.x); fma2(c1q, wA[33 + 2*i], vb.y);

                ulonglong2 ha = h1a[i]; ulonglong2 hb = h1b[i];
                ulonglong2 wsm = whp[i * 256 + t];
                fma2(q00, wsm.x, ha.x); fma2(q01, wsm.y, ha.y);
                fma2(q10, wsm.x, hb.x); fma2(q11, wsm.y, hb.y);
                if (s > 0) {                      // M@h1 reuses ha/hb registers
                    fma2(a0, wA[2*i], ha.x); fma2(a1, wA[2*i+1], ha.y);
                    fma2(c0q, wA[2*i], hb.x); fma2(c1q, wA[2*i+1], hb.y);
                }
            }
            float ga, gb;
            if (s > 0) {
                ga = psum(a0) + psum(a1) + b0fold;
                gb = psum(c0q) + psum(c1q) + b0fold;
            } else {
                ga = psum(a0) + psum(a1) + bias0;
                gb = psum(c0q) + psum(c1q) + bias0;
            }
            p0 = psum(q00) + psum(q01) + bias1;
            p1 = psum(q10) + psum(q11) + bias1;
            sG[t] = ga; sG[256 + t] = gb;
        }
        __syncthreads();

        // ---- P2: act0 (t<128) || FC(h1[s-1]) -> out[s-1] (t>=128, s>0) ----
        if (t < 128) {
            const float* gq = sG + ab * 256;
            h0w[ab * 64 + aj] = cellact(gq[aj], gq[64 + aj], gq[128 + aj], gq[192 + aj], c0);
        } else if (s > 0) {
            const ulonglong2* hA = (const ulonglong2*)(h1r);
            const ulonglong2* hB = (const ulonglong2*)(h1r + 64);
            unsigned long long fA0 = 0, fA1 = 0, fB0 = 0, fB1 = 0;
            #pragma unroll
            for (int c = 0; c < 16; c += 2) {
                ulonglong2 w0c = wfc[c * 128 + u];
                ulonglong2 w1c = wfc[(c + 1) * 128 + u];
                ulonglong2 a0v = hA[c], a1v = hA[c + 1];
                ulonglong2 b0v = hB[c], b1v = hB[c + 1];
                fma2(fA0, w0c.x, a0v.x); fma2(fA1, w0c.y, a0v.y);
                fma2(fA0, w1c.x, a1v.x); fma2(fA1, w1c.y, a1v.y);
                fma2(fB0, w0c.x, b0v.x); fma2(fB1, w0c.y, b0v.y);
                fma2(fB0, w1c.x, b1v.x); fma2(fB1, w1c.y, b1v.y);
            }
            out[((size_t)(b0 + 0) * Tn + (s - 1)) * 128 + u] = psum(fA0) + psum(fA1) + sFCb[u];
            out[((size_t)(b0 + 1) * Tn + (s - 1)) * 128 + u] = psum(fB0) + psum(fB1) + sFCb[u];
        }
        __syncthreads();

        // ---- P3: gates1 = Wih1@h0[s] (regs) + p + bias already in p ----
        {
            const ulonglong2* h0a = (const ulonglong2*)(h0w);
            const ulonglong2* h0b = (const ulonglong2*)(h0w + 64);
            unsigned long long q00 = 0, q01 = 0, q10 = 0, q11 = 0;
            #pragma unroll
            for (int i = 0; i < 16; i++) {
                ulonglong2 va = h0a[i]; ulonglong2 vb = h0b[i];
                fma2(q00, wC[2*i], va.x); fma2(q01, wC[2*i+1], va.y);
                fma2(q10, wC[2*i], vb.x); fma2(q11, wC[2*i+1], vb.y);
            }
            sG[t]       = psum(q00) + psum(q01) + p0;
            sG[256 + t] = psum(q10) + psum(q11) + p1;
        }
        __syncthreads();

        // ---- P4: act1 (t<128) ----
        if (t < 128) {
            const float* gq = sG + ab * 256;
            h1w[ab * 64 + aj] = cellact(gq[aj], gq[64 + aj], gq[128 + aj], gq[192 + aj], c1);
        }
        __syncthreads();
    }

    // final FC for h1[T-1] (parity 0 after s=1023)
    if (t >= 128) {
        const float* h1f = sH1;
        const ulonglong2* hA = (const ulonglong2*)(h1f);
        const ulonglong2* hB = (const ulonglong2*)(h1f + 64);
        unsigned long long fA0 = 0, fA1 = 0, fB0 = 0, fB1 = 0;
        #pragma unroll
        for (int c = 0; c < 16; c += 2) {
            ulonglong2 w0c = wfc[c * 128 + u];
            ulonglong2 w1c = wfc[(c + 1) * 128 + u];
            ulonglong2 a0v = hA[c], a1v = hA[c + 1];
            ulonglong2 b0v = hB[c], b1v = hB[c + 1];
            fma2(fA0, w0c.x, a0v.x); fma2(fA1, w0c.y, a0v.y);
            fma2(fA0, w1c.x, a1v.x); fma2(fA1, w1c.y, a1v.y);
            fma2(fB0, w0c.x, b0v.x); fma2(fB1, w0c.y, b0v.y);
            fma2(fB0, w1c.x, b1v.x); fma2(fB1, w1c.y, b1v.y);
        }
        out[((size_t)(b0 + 0) * Tn + (Tn - 1)) * 128 + u] = psum(fA0) + psum(fA1) + sFCb[u];
        out[((size_t)(b0 + 1) * Tn + (Tn - 1)) * 128 + u] = psum(fB0) + psum(fB1) + sFCb[u];
    }
}

extern "C" void kernel_launch(void* const* d_in, const int* in_sizes, int n_in,
                              void* d_out, int out_size) {
    (void)in_sizes; (void)n_in; (void)out_size;
    const float* x    = (const float*)d_in[0];
    const float* eW0i = (const float*)d_in[1];
    const float* eW0h = (const float*)d_in[2];
    const float* eb0i = (const float*)d_in[3];
    const float* eb0h = (const float*)d_in[4];
    const float* eW1i = (const float*)d_in[5];
    const float* eW1h = (const float*)d_in[6];
    const float* eb1i = (const float*)d_in[7];
    const float* eb1h = (const float*)d_in[8];
    const float* dW0i = (const float*)d_in[9];
    const float* dW0h = (const float*)d_in[10];
    const float* db0i = (const float*)d_in[11];
    const float* db0h = (const float*)d_in[12];
    const float* dW1i = (const float*)d_in[13];
    const float* dW1h = (const float*)d_in[14];
    const float* db1i = (const float*)d_in[15];
    const float* db1h = (const float*)d_in[16];
    const float* fcW  = (const float*)d_in[17];
    const float* fcb  = (const float*)d_in[18];

    prep_kernel<<<64, 256>>>(dW0i, fcW);
    dim3 pgrid(256, 32);
    prep_x_kernel<<<pgrid, 256>>>(x, eW0i, eb0i, eb0h);

    cudaFuncSetAttribute(lstm_ae_kernel, cudaFuncAttributeMaxDynamicSharedMemorySize,
                         SMEM_FLOATS * (int)sizeof(float));
    lstm_ae_kernel<<<128, 256, SMEM_FLOATS * sizeof(float)>>>(
        x, eW0i, eW0h, eb0i, eb0h, eW1i, eW1h, eb1i, eb1h,
        dW0i, dW0h, db0i, db0h, dW1i, dW1h, db1i, db1h,
        fcW, fcb, (float*)d_out);
}